// round 12
// baseline (speedup 1.0000x reference)
#include <cuda_runtime.h>
#include <cuda_bf16.h>

#define MCTA 16
#define NCTAS 128
#define NTHREADS 512
#define NWARPS 16
#define T_STEPS 128
#define KSTEPS 17
#define PFD 6            // prefetch distance (ksteps) ~ 240 cyc
#define ACT_STRIDE 280   // bf16 elems per row (conflict-free ldmatrix)

// Packed weights, fragment order. Tile map (16 warps):
//   T in [0,32):    GEMM1 (Wm0), warp w owns T = 2w, 2w+1 (N cols [16w,16w+16))
//   T in [32,160):  per-warp P3 block: q=T-32, w=q/8, j=q%8
//                   j<6  -> GEMM2 tile tg=(6w+j)  (Wf10|Wf20|Wh0, n2=8*tg)
//                   j>=6 -> GEMM3 (Wm1) n-tile 2w+(j-6)
__device__ uint2 g_Wpk[160 * 17 * 32];
__device__ float4 g_smallW4[768];

// ---------------------------------------------------------------------------
// Activation column layout (padded K = 272):
//   0..255: c / cu / c_new    256..257: meas/60    258..261: s/60   262..271: 0
// Row remap: type0 (Wm0,Wf10,Wf20;fin260): k<256->k, 258..261->k-2
//            type1 (Wh0;fin262): k<256->k, 256,257->k+4, 258..261->k-2
//            type2 (Wm1;fin262): identity
// ---------------------------------------------------------------------------
__global__ void prepack_kernel(
    const float* __restrict__ Wm0, const float* __restrict__ Wf10,
    const float* __restrict__ Wf20, const float* __restrict__ Wh0,
    const float* __restrict__ Wm1, const float* __restrict__ Wf11,
    const float* __restrict__ Wf21, const float* __restrict__ Wh1)
{
    const int total_u32 = 160 * 17 * 32 * 2;
    int idx = blockIdx.x * blockDim.x + threadIdx.x;
    if (idx < total_u32) {
        int r    = idx & 1;
        int lane = (idx >> 1) & 31;
        int tk   = idx >> 6;          // tile*17 + ks
        int ks   = tk % 17;
        int tile = tk / 17;
        int kk = ks * 16 + (lane & 3) * 2 + r * 8;
        const float* W; int type; int ncol;
        if (tile < 32) {
            W = Wm0; type = 0; ncol = tile * 8 + (lane >> 2);
        } else {
            int q = tile - 32, wq = q >> 3, j = q & 7;
            if (j < 6) {
                int n2 = (wq * 6 + j) * 8 + (lane >> 2);
                if (n2 < 256)      { W = Wf10; type = 0; ncol = n2; }
                else if (n2 < 512) { W = Wf20; type = 0; ncol = n2 - 256; }
                else               { W = Wh0;  type = 1; ncol = n2 - 512; }
            } else {
                W = Wm1; type = 2; ncol = (wq * 2 + (j - 6)) * 8 + (lane >> 2);
            }
        }
        auto srcrow = [&](int k) -> int {
            if (type == 0) return k < 256 ? k : ((k >= 258 && k < 262) ? k - 2 : -1);
            if (type == 1) return k < 256 ? k : (k < 258 ? k + 4 : (k < 262 ? k - 2 : -1));
            return k < 262 ? k : -1;
        };
        int s0 = srcrow(kk), s1 = srcrow(kk + 1);
        float v0 = (s0 >= 0) ? W[(size_t)s0 * 256 + ncol] : 0.f;
        float v1 = (s1 >= 0) ? W[(size_t)s1 * 256 + ncol] : 0.f;
        __nv_bfloat162 p;
        p.x = __float2bfloat16(v0);
        p.y = __float2bfloat16(v1);
        reinterpret_cast<unsigned*>(g_Wpk)[idx] = *reinterpret_cast<unsigned*>(&p);
    } else if (idx < total_u32 + 768) {
        int j = idx - total_u32;
        float4 v = make_float4(0.f, 0.f, 0.f, 0.f);
        if (j < 256)      { v.x = Wf11[j * 2];        v.y = Wf11[j * 2 + 1]; }
        else if (j < 512) { int q = j - 256;
                            v.x = Wf21[q * 4]; v.y = Wf21[q * 4 + 1];
                            v.z = Wf21[q * 4 + 2]; v.w = Wf21[q * 4 + 3]; }
        else              { int q = j - 512;
                            v.x = Wh1[q * 2];  v.y = Wh1[q * 2 + 1]; }
        g_smallW4[j] = v;
    }
}

// ---------------------------------------------------------------------------
__device__ __forceinline__ void mma16816(float* d, const unsigned* a, uint2 b) {
    asm volatile(
        "mma.sync.aligned.m16n8k16.row.col.f32.bf16.bf16.f32 "
        "{%0,%1,%2,%3}, {%4,%5,%6,%7}, {%8,%9}, {%0,%1,%2,%3};\n"
        : "+f"(d[0]), "+f"(d[1]), "+f"(d[2]), "+f"(d[3])
        : "r"(a[0]), "r"(a[1]), "r"(a[2]), "r"(a[3]), "r"(b.x), "r"(b.y));
}
__device__ __forceinline__ void ldmA(unsigned* a, unsigned addr) {
    asm volatile(
        "ldmatrix.sync.aligned.m8n8.x4.shared.b16 {%0,%1,%2,%3}, [%4];\n"
        : "=r"(a[0]), "=r"(a[1]), "=r"(a[2]), "=r"(a[3]) : "r"(addr));
}
__device__ __forceinline__ void pfL1(const void* p) {
    asm volatile("prefetch.global.L1 [%0];\n" :: "l"(p));
}
__device__ __forceinline__ float tanha(float x) {
    float y; asm("tanh.approx.f32 %0, %1;" : "=f"(y) : "f"(x)); return y;
}
__device__ __forceinline__ unsigned packbf2(float a, float b) {
    __nv_bfloat162 h;
    h.x = __float2bfloat16(a);
    h.y = __float2bfloat16(b);
    return *reinterpret_cast<unsigned*>(&h);
}

__device__ __forceinline__ void write_act_tanh(int ntile, int cbase, int row0,
        const float (&D)[4], const float* __restrict__ bias,
        __nv_bfloat16 (*actp)[ACT_STRIDE]) {
    int col = ntile * 8 + cbase;
    float bv0 = bias[col], bv1 = bias[col + 1];
    __nv_bfloat162 h0, h1;
    h0.x = __float2bfloat16(tanha(D[0] + bv0));
    h0.y = __float2bfloat16(tanha(D[1] + bv1));
    h1.x = __float2bfloat16(tanha(D[2] + bv0));
    h1.y = __float2bfloat16(tanha(D[3] + bv1));
    *reinterpret_cast<__nv_bfloat162*>(&actp[row0][col]) = h0;
    *reinterpret_cast<__nv_bfloat162*>(&actp[row0 + 8][col]) = h1;
}

__device__ __forceinline__ void g2_epilogue(int tg, int cbase,
        const float (&D)[4], const float* __restrict__ bias2s,
        const float4* __restrict__ smallWs, float (&o)[2][8]) {
    int col = tg * 8 + cbase;
    int seg = tg >> 5;  // 0: Wf11 (d), 1: Wf21 (pv), 2: Wh1 (hv)
    float bb0 = bias2s[col], bb1 = bias2s[col + 1];
    float4 w0 = smallWs[col];
    float4 w1 = smallWs[col + 1];
    int ob = (seg == 0) ? 0 : ((seg == 1) ? 2 : 6);
    float h0 = tanha(D[0] + bb0);
    float h1 = tanha(D[1] + bb1);
    float h2 = tanha(D[2] + bb0);
    float h3 = tanha(D[3] + bb1);
    o[0][ob + 0] += h0 * w0.x + h1 * w1.x;
    o[0][ob + 1] += h0 * w0.y + h1 * w1.y;
    o[1][ob + 0] += h2 * w0.x + h3 * w1.x;
    o[1][ob + 1] += h2 * w0.y + h3 * w1.y;
    if (seg == 1) {
        o[0][ob + 2] += h0 * w0.z + h1 * w1.z;
        o[0][ob + 3] += h0 * w0.w + h1 * w1.w;
        o[1][ob + 2] += h2 * w0.z + h3 * w1.z;
        o[1][ob + 3] += h2 * w0.w + h3 * w1.w;
    }
}

// ---------------------------------------------------------------------------
// Main persistent kernel: 128 CTAs x 512 threads, 16 batch rows per CTA.
// R5 champion structure (5 barriers) + zero-register L1 prefetch.
// ---------------------------------------------------------------------------
__global__ void __launch_bounds__(NTHREADS, 1) egbrnn_main(
    const float* __restrict__ x, const float* __restrict__ target,
    const float* __restrict__ c0,
    const float* __restrict__ bm0, const float* __restrict__ bm1,
    const float* __restrict__ bf10, const float* __restrict__ bf11,
    const float* __restrict__ bf20, const float* __restrict__ bf21,
    const float* __restrict__ bh0, const float* __restrict__ bh1,
    float* __restrict__ out)
{
    __shared__ __align__(16) __nv_bfloat16 act[MCTA][ACT_STRIDE];
    __shared__ float sS[MCTA][4];
    __shared__ float Pm[MCTA][16];
    __shared__ __align__(16) float part[NWARPS][MCTA][12];
    __shared__ float bm0s[256], bm1s[256], bias2s[768], biasSs[8];
    __shared__ __align__(16) float4 smallWs[768];

    const int tid = threadIdx.x;
    const int w = tid >> 5, lane = tid & 31;
    const int b0 = blockIdx.x * MCTA;
    const int row0 = lane >> 2;
    const int cbase = (lane & 3) * 2;

    // ---- one-time shared init ----
    if (tid < 256) { bm0s[tid] = bm0[tid]; bm1s[tid] = bm1[tid]; }
    for (int i = tid; i < 768; i += NTHREADS) {
        bias2s[i] = (i < 256) ? bf10[i] : (i < 512 ? bf20[i - 256] : bh0[i - 512]);
        smallWs[i] = g_smallW4[i];
    }
    if (tid < 8)
        biasSs[tid] = (tid < 2) ? bf11[tid] : (tid < 6 ? bf21[tid - 2] : bh1[tid - 6]);
    for (int i = tid; i < MCTA * 24; i += NTHREADS) {   // zero cols 256..279
        int r = i / 24, c = 256 + i % 24;
        act[r][c] = __float2bfloat16(0.f);
    }
    for (int i = tid; i < MCTA * 256; i += NTHREADS) {  // c = c0
        int r = i >> 8, j = i & 255;
        act[r][j] = __float2bfloat16(c0[(size_t)(b0 + r) * 256 + j]);
    }
    __syncthreads();
    if (tid < MCTA) {
        int r = tid;
        float4 tg = *reinterpret_cast<const float4*>(
            &target[((size_t)(b0 + r) * T_STEPS) * 4]);
        sS[r][0] = tg.x; sS[r][1] = tg.y; sS[r][2] = tg.z; sS[r][3] = tg.w;
#pragma unroll
        for (int i = 0; i < 16; i++) Pm[r][i] = (i % 5 == 0) ? 1.f : 0.f;
        *reinterpret_cast<unsigned*>(&act[r][258]) =
            packbf2(tg.x * (1.f / 60.f), tg.y * (1.f / 60.f));
        *reinterpret_cast<unsigned*>(&act[r][260]) =
            packbf2(tg.z * (1.f / 60.f), tg.w * (1.f / 60.f));
    }
    __syncthreads();

    const unsigned ab0 =
        (unsigned)__cvta_generic_to_shared(&act[lane & 15][(lane >> 4) * 8]);
    const uint2* wG1 = g_Wpk + (2 * w) * KSTEPS * 32 + lane;
    const uint2* wP3 = g_Wpk + (32 + 8 * w) * KSTEPS * 32 + lane;

    float2 xcur, xnxt;   // meas prefetch (meaningful for tid<16 only)
    if (tid < MCTA)
        xcur = *reinterpret_cast<const float2*>(
            &x[((size_t)(b0 + tid)) * T_STEPS * 2]);

    for (int t = 0; t < T_STEPS; t++) {
        // ---- P1: GEMM1 (cu preactivation), 2 tiles/warp + L1 prefetch ----
        float D1[2][4];
#pragma unroll
        for (int i = 0; i < 2; i++)
            D1[i][0] = D1[i][1] = D1[i][2] = D1[i][3] = 0.f;
        {
            unsigned a[2][4];
            uint2 b1[2][2];
            b1[0][0] = wG1[0];
            b1[1][0] = wG1[KSTEPS * 32];
            b1[0][1] = wG1[32];
            b1[1][1] = wG1[(KSTEPS + 1) * 32];
            ldmA(a[0], ab0);
#pragma unroll
            for (int ks = 0; ks < KSTEPS; ks++) {
                if (ks + 1 < KSTEPS)
                    ldmA(a[(ks + 1) & 1], ab0 + (unsigned)(ks + 1) * 32u);
                if (ks + PFD < KSTEPS) {
                    pfL1(wG1 + (0 * KSTEPS + ks + PFD) * 32);
                    pfL1(wG1 + (1 * KSTEPS + ks + PFD) * 32);
                }
                mma16816(D1[0], a[ks & 1], b1[0][ks & 1]);
                mma16816(D1[1], a[ks & 1], b1[1][ks & 1]);
                if (ks + 2 < KSTEPS) {
                    b1[0][ks & 1] = wG1[(0 * KSTEPS + ks + 2) * 32];
                    b1[1][ks & 1] = wG1[(1 * KSTEPS + ks + 2) * 32];
                }
            }
        }
        __syncthreads();

        // ---- P2: write cu over c; m2 from prefetched meas; b3l loads ----
        write_act_tanh(2 * w,     cbase, row0, D1[0], bm0s, act);
        write_act_tanh(2 * w + 1, cbase, row0, D1[1], bm0s, act);
        uint2 b3l[2];
        b3l[0] = wP3[(6 * KSTEPS + 16) * 32];
        b3l[1] = wP3[(7 * KSTEPS + 16) * 32];
        if (tid < MCTA) {
            *reinterpret_cast<unsigned*>(&act[tid][256]) =
                packbf2(xcur.x * (1.f / 60.f), xcur.y * (1.f / 60.f));
            int tn = (t + 1 < T_STEPS) ? t + 1 : t;
            xnxt = *reinterpret_cast<const float2*>(
                &x[(((size_t)(b0 + tid)) * T_STEPS + tn) * 2]);
        }
        __syncthreads();

        // ---- P3: fused GEMM2 (6) + GEMM3 ks0..15 (2) + L1 prefetch ------
        float D2[8][4];
#pragma unroll
        for (int i = 0; i < 8; i++)
            D2[i][0] = D2[i][1] = D2[i][2] = D2[i][3] = 0.f;
        {
            unsigned a[2][4];
            uint2 b[8][2];
#pragma unroll
            for (int i = 0; i < 8; i++) {
                b[i][0] = wP3[(i * KSTEPS + 0) * 32];
                b[i][1] = wP3[(i * KSTEPS + 1) * 32];
            }
            ldmA(a[0], ab0);
#pragma unroll
            for (int ks = 0; ks < KSTEPS; ks++) {
                if (ks + 1 < KSTEPS)
                    ldmA(a[(ks + 1) & 1], ab0 + (unsigned)(ks + 1) * 32u);
#pragma unroll
                for (int i = 0; i < 8; i++) {
                    if (ks + PFD < KSTEPS)
                        pfL1(wP3 + (i * KSTEPS + ks + PFD) * 32);
                    if (i < 6 || ks < KSTEPS - 1)
                        mma16816(D2[i], a[ks & 1], b[i][ks & 1]);
                    if (ks + 2 < KSTEPS)
                        b[i][ks & 1] = wP3[(i * KSTEPS + ks + 2) * 32];
                }
            }
        }
        float o[2][8];
#pragma unroll
        for (int s = 0; s < 2; s++)
#pragma unroll
            for (int k = 0; k < 8; k++) o[s][k] = 0.f;
#pragma unroll
        for (int j = 0; j < 6; j++)
            g2_epilogue(6 * w + j, cbase, D2[j], bias2s, smallWs, o);
#pragma unroll
        for (int s = 0; s < 2; s++)
#pragma unroll
            for (int k = 0; k < 8; k++) {
                o[s][k] += __shfl_xor_sync(0xffffffffu, o[s][k], 1);
                o[s][k] += __shfl_xor_sync(0xffffffffu, o[s][k], 2);
            }
        if ((lane & 3) == 0) {
            float4* p0 = reinterpret_cast<float4*>(part[w][row0]);
            float4* p1 = reinterpret_cast<float4*>(part[w][row0 + 8]);
            p0[0] = make_float4(o[0][0], o[0][1], o[0][2], o[0][3]);
            p0[1] = make_float4(o[0][4], o[0][5], o[0][6], o[0][7]);
            p1[0] = make_float4(o[1][0], o[1][1], o[1][2], o[1][3]);
            p1[1] = make_float4(o[1][4], o[1][5], o[1][6], o[1][7]);
        }
        __syncthreads();

        // ---- P4: per-row Kalman update (fp32), tid<16, float4 reduce ----
        if (tid < MCTA) {
            const int r = tid;
            float sm[8];
#pragma unroll
            for (int k = 0; k < 8; k++) sm[k] = biasSs[k];
#pragma unroll
            for (int ww = 0; ww < NWARPS; ww++) {
                const float4* pp = reinterpret_cast<const float4*>(part[ww][r]);
                float4 v0 = pp[0], v1 = pp[1];
                sm[0] += v0.x; sm[1] += v0.y; sm[2] += v0.z; sm[3] += v0.w;
                sm[4] += v1.x; sm[5] += v1.y; sm[6] += v1.z; sm[7] += v1.w;
            }
            const float d0 = sm[0], d1 = sm[1];
            const float pv[4] = {sm[2], sm[3], sm[4], sm[5]};
            const float hv0 = sm[6], hv1 = sm[7];
            float s0 = sS[r][0], s1 = sS[r][1], s2 = sS[r][2], s3 = sS[r][3];
            float sp[4];
            sp[0] = s0 + s2 + 0.5f * d0;
            sp[1] = s1 + s3 + 0.5f * d1;
            sp[2] = s2 + d0;
            sp[3] = s3 + d1;
            float P[4][4];
#pragma unroll
            for (int i = 0; i < 4; i++)
#pragma unroll
                for (int j = 0; j < 4; j++) P[i][j] = Pm[r][i * 4 + j];
            float FP[4][4], Pp[4][4];
#pragma unroll
            for (int j = 0; j < 4; j++) {
                FP[0][j] = P[0][j] + P[2][j];
                FP[1][j] = P[1][j] + P[3][j];
                FP[2][j] = P[2][j];
                FP[3][j] = P[3][j];
            }
#pragma unroll
            for (int i = 0; i < 4; i++) {
                Pp[i][0] = FP[i][0] + FP[i][2];
                Pp[i][1] = FP[i][1] + FP[i][3];
                Pp[i][2] = FP[i][2];
                Pp[i][3] = FP[i][3];
            }
#pragma unroll
            for (int i = 0; i < 4; i++)
#pragma unroll
                for (int j = 0; j < 4; j++) Pp[i][j] += pv[i] * pv[j];
#pragma unroll
            for (int i = 0; i < 4; i++) Pp[i][i] += 0.01f;
            float m0 = xcur.x, m1 = xcur.y;
            float in0 = m0 - sp[0], in1 = m1 - sp[1];
            float S00 = Pp[0][0] + hv0 * hv0 + 1.f;
            float S01 = Pp[0][1] + hv0 * hv1;
            float S10 = Pp[1][0] + hv1 * hv0;
            float S11 = Pp[1][1] + hv1 * hv1 + 1.f;
            float inv = 1.0f / (S00 * S11 - S01 * S10);
            float K[4][2], KS[4][2], su[4];
#pragma unroll
            for (int i = 0; i < 4; i++) {
                K[i][0] = (Pp[i][0] * S11 - Pp[i][1] * S10) * inv;
                K[i][1] = (Pp[i][1] * S00 - Pp[i][0] * S01) * inv;
                su[i] = sp[i] + K[i][0] * in0 + K[i][1] * in1;
                KS[i][0] = K[i][0] * S00 + K[i][1] * S10;
                KS[i][1] = K[i][0] * S01 + K[i][1] * S11;
            }
#pragma unroll
            for (int i = 0; i < 4; i++)
#pragma unroll
                for (int j = 0; j < 4; j++)
                    Pm[r][i * 4 + j] =
                        Pp[i][j] - KS[i][0] * K[j][0] - KS[i][1] * K[j][1];
            sS[r][0] = su[0]; sS[r][1] = su[1];
            sS[r][2] = su[2]; sS[r][3] = su[3];
            *reinterpret_cast<float4*>(
                &out[(((size_t)(b0 + r)) * T_STEPS + t) * 4]) =
                make_float4(su[0], su[1], su[2], su[3]);
            *reinterpret_cast<unsigned*>(&act[r][258]) =
                packbf2(su[0] * (1.f / 60.f), su[1] * (1.f / 60.f));
            *reinterpret_cast<unsigned*>(&act[r][260]) =
                packbf2(su[2] * (1.f / 60.f), su[3] * (1.f / 60.f));
            xcur = xnxt;
        }
        __syncthreads();

        // ---- P5: GEMM3 final kstep (reads tail cols 256..271) + c_new.
        //      Reads only cols 256..271, writes only cols 0..255: disjoint. ----
        {
            unsigned a0[4];
            ldmA(a0, ab0 + 16u * 32u);
            mma16816(D2[6], a0, b3l[0]);
            mma16816(D2[7], a0, b3l[1]);
        }
        write_act_tanh(2 * w,     cbase, row0, D2[6], bm1s, act);
        write_act_tanh(2 * w + 1, cbase, row0, D2[7], bm1s, act);
        __syncthreads();
    }
}

// ---------------------------------------------------------------------------
extern "C" void kernel_launch(void* const* d_in, const int* in_sizes, int n_in,
                              void* d_out, int out_size)
{
    const float* x    = (const float*)d_in[0];
    const float* targ = (const float*)d_in[1];
    const float* c0   = (const float*)d_in[2];
    const float* Wm0  = (const float*)d_in[3];
    const float* bm0  = (const float*)d_in[4];
    const float* Wm1  = (const float*)d_in[5];
    const float* bm1  = (const float*)d_in[6];
    const float* Wf10 = (const float*)d_in[7];
    const float* bf10 = (const float*)d_in[8];
    const float* Wf11 = (const float*)d_in[9];
    const float* bf11 = (const float*)d_in[10];
    const float* Wf20 = (const float*)d_in[11];
    const float* bf20 = (const float*)d_in[12];
    const float* Wf21 = (const float*)d_in[13];
    const float* bf21 = (const float*)d_in[14];
    const float* Wh0  = (const float*)d_in[15];
    const float* bh0  = (const float*)d_in[16];
    const float* Wh1  = (const float*)d_in[17];
    const float* bh1  = (const float*)d_in[18];
    float* out = (float*)d_out;

    const int tot = 160 * 17 * 32 * 2 + 768;
    prepack_kernel<<<(tot + 255) / 256, 256>>>(Wm0, Wf10, Wf20, Wh0, Wm1,
                                               Wf11, Wf21, Wh1);
    egbrnn_main<<<NCTAS, NTHREADS>>>(x, targ, c0, bm0, bm1, bf10, bf11,
                                     bf20, bf21, bh0, bh1, out);
}

// round 13
// speedup vs baseline: 1.0177x; 1.0177x over previous
#include <cuda_runtime.h>
#include <cuda_bf16.h>

#define MCTA 16
#define NCTAS 128
#define NTHREADS 1024
#define NWARPS 32
#define T_STEPS 128
#define KSTEPS 17
#define ACT_STRIDE 280   // bf16 elems per row (conflict-free ldmatrix)

// Packed weights, fragment order. Tile map (32 warps):
//   T in [0,32):    GEMM1 (Wm0), warp w owns tile w (N cols [8w,8w+8))
//   T in [32,160):  per-warp P3 block: q=T-32, w=q/4, j=q%4
//                   j<3  -> GEMM2 tile tg=(3w+j)  (Wf10|Wf20|Wh0, n2=8*tg)
//                   j==3 -> GEMM3 (Wm1) n-tile w
__device__ uint2 g_Wpk[160 * 17 * 32];
__device__ float4 g_smallW4[768];

// ---------------------------------------------------------------------------
// Activation column layout (padded K = 272):
//   0..255: c / cu / c_new    256..257: meas/60    258..261: s/60   262..271: 0
// Row remap: type0 (Wm0,Wf10,Wf20;fin260): k<256->k, 258..261->k-2
//            type1 (Wh0;fin262): k<256->k, 256,257->k+4, 258..261->k-2
//            type2 (Wm1;fin262): identity
// ---------------------------------------------------------------------------
__global__ void prepack_kernel(
    const float* __restrict__ Wm0, const float* __restrict__ Wf10,
    const float* __restrict__ Wf20, const float* __restrict__ Wh0,
    const float* __restrict__ Wm1, const float* __restrict__ Wf11,
    const float* __restrict__ Wf21, const float* __restrict__ Wh1)
{
    const int total_u32 = 160 * 17 * 32 * 2;
    int idx = blockIdx.x * blockDim.x + threadIdx.x;
    if (idx < total_u32) {
        int r    = idx & 1;
        int lane = (idx >> 1) & 31;
        int tk   = idx >> 6;          // tile*17 + ks
        int ks   = tk % 17;
        int tile = tk / 17;
        int kk = ks * 16 + (lane & 3) * 2 + r * 8;
        const float* W; int type; int ncol;
        if (tile < 32) {
            W = Wm0; type = 0; ncol = tile * 8 + (lane >> 2);
        } else {
            int q = tile - 32, wq = q >> 2, j = q & 3;
            if (j < 3) {
                int n2 = (wq * 3 + j) * 8 + (lane >> 2);
                if (n2 < 256)      { W = Wf10; type = 0; ncol = n2; }
                else if (n2 < 512) { W = Wf20; type = 0; ncol = n2 - 256; }
                else               { W = Wh0;  type = 1; ncol = n2 - 512; }
            } else {
                W = Wm1; type = 2; ncol = wq * 8 + (lane >> 2);
            }
        }
        auto srcrow = [&](int k) -> int {
            if (type == 0) return k < 256 ? k : ((k >= 258 && k < 262) ? k - 2 : -1);
            if (type == 1) return k < 256 ? k : (k < 258 ? k + 4 : (k < 262 ? k - 2 : -1));
            return k < 262 ? k : -1;
        };
        int s0 = srcrow(kk), s1 = srcrow(kk + 1);
        float v0 = (s0 >= 0) ? W[(size_t)s0 * 256 + ncol] : 0.f;
        float v1 = (s1 >= 0) ? W[(size_t)s1 * 256 + ncol] : 0.f;
        __nv_bfloat162 p;
        p.x = __float2bfloat16(v0);
        p.y = __float2bfloat16(v1);
        reinterpret_cast<unsigned*>(g_Wpk)[idx] = *reinterpret_cast<unsigned*>(&p);
    } else if (idx < total_u32 + 768) {
        int j = idx - total_u32;
        float4 v = make_float4(0.f, 0.f, 0.f, 0.f);
        if (j < 256)      { v.x = Wf11[j * 2];        v.y = Wf11[j * 2 + 1]; }
        else if (j < 512) { int q = j - 256;
                            v.x = Wf21[q * 4]; v.y = Wf21[q * 4 + 1];
                            v.z = Wf21[q * 4 + 2]; v.w = Wf21[q * 4 + 3]; }
        else              { int q = j - 512;
                            v.x = Wh1[q * 2];  v.y = Wh1[q * 2 + 1]; }
        g_smallW4[j] = v;
    }
}

// ---------------------------------------------------------------------------
__device__ __forceinline__ void mma16816(float* d, const unsigned* a, uint2 b) {
    asm volatile(
        "mma.sync.aligned.m16n8k16.row.col.f32.bf16.bf16.f32 "
        "{%0,%1,%2,%3}, {%4,%5,%6,%7}, {%8,%9}, {%0,%1,%2,%3};\n"
        : "+f"(d[0]), "+f"(d[1]), "+f"(d[2]), "+f"(d[3])
        : "r"(a[0]), "r"(a[1]), "r"(a[2]), "r"(a[3]), "r"(b.x), "r"(b.y));
}
__device__ __forceinline__ void ldmA(unsigned* a, unsigned addr) {
    asm volatile(
        "ldmatrix.sync.aligned.m8n8.x4.shared.b16 {%0,%1,%2,%3}, [%4];\n"
        : "=r"(a[0]), "=r"(a[1]), "=r"(a[2]), "=r"(a[3]) : "r"(addr));
}
__device__ __forceinline__ float tanha(float x) {
    float y; asm("tanh.approx.f32 %0, %1;" : "=f"(y) : "f"(x)); return y;
}
__device__ __forceinline__ unsigned packbf2(float a, float b) {
    __nv_bfloat162 h;
    h.x = __float2bfloat16(a);
    h.y = __float2bfloat16(b);
    return *reinterpret_cast<unsigned*>(&h);
}

__device__ __forceinline__ void write_act_tanh(int ntile, int cbase, int row0,
        const float (&D)[4], const float* __restrict__ bias,
        __nv_bfloat16 (*actp)[ACT_STRIDE]) {
    int col = ntile * 8 + cbase;
    float bv0 = bias[col], bv1 = bias[col + 1];
    __nv_bfloat162 h0, h1;
    h0.x = __float2bfloat16(tanha(D[0] + bv0));
    h0.y = __float2bfloat16(tanha(D[1] + bv1));
    h1.x = __float2bfloat16(tanha(D[2] + bv0));
    h1.y = __float2bfloat16(tanha(D[3] + bv1));
    *reinterpret_cast<__nv_bfloat162*>(&actp[row0][col]) = h0;
    *reinterpret_cast<__nv_bfloat162*>(&actp[row0 + 8][col]) = h1;
}

__device__ __forceinline__ void g2_epilogue(int tg, int cbase,
        const float (&D)[4], const float* __restrict__ bias2s,
        const float4* __restrict__ smallWs, float (&o)[2][8]) {
    int col = tg * 8 + cbase;
    int seg = tg >> 5;  // 0: Wf11 (d), 1: Wf21 (pv), 2: Wh1 (hv)
    float bb0 = bias2s[col], bb1 = bias2s[col + 1];
    float4 w0 = smallWs[col];
    float4 w1 = smallWs[col + 1];
    int ob = (seg == 0) ? 0 : ((seg == 1) ? 2 : 6);
    float h0 = tanha(D[0] + bb0);
    float h1 = tanha(D[1] + bb1);
    float h2 = tanha(D[2] + bb0);
    float h3 = tanha(D[3] + bb1);
    o[0][ob + 0] += h0 * w0.x + h1 * w1.x;
    o[0][ob + 1] += h0 * w0.y + h1 * w1.y;
    o[1][ob + 0] += h2 * w0.x + h3 * w1.x;
    o[1][ob + 1] += h2 * w0.y + h3 * w1.y;
    if (seg == 1) {
        o[0][ob + 2] += h0 * w0.z + h1 * w1.z;
        o[0][ob + 3] += h0 * w0.w + h1 * w1.w;
        o[1][ob + 2] += h2 * w0.z + h3 * w1.z;
        o[1][ob + 3] += h2 * w0.w + h3 * w1.w;
    }
}

// ---------------------------------------------------------------------------
// Main persistent kernel: 128 CTAs x 1024 threads (32 warps), 16 rows/CTA.
// Same 5-barrier R5 structure; per-warp tile load halved (G1:1, P3:4),
// warps/SMSP doubled to 8 for latency coverage. Reg cap 64.
// ---------------------------------------------------------------------------
__global__ void __launch_bounds__(NTHREADS, 1) egbrnn_main(
    const float* __restrict__ x, const float* __restrict__ target,
    const float* __restrict__ c0,
    const float* __restrict__ bm0, const float* __restrict__ bm1,
    const float* __restrict__ bf10, const float* __restrict__ bf11,
    const float* __restrict__ bf20, const float* __restrict__ bf21,
    const float* __restrict__ bh0, const float* __restrict__ bh1,
    float* __restrict__ out)
{
    __shared__ __align__(16) __nv_bfloat16 act[MCTA][ACT_STRIDE];
    __shared__ float sS[MCTA][4];
    __shared__ float Pm[MCTA][16];
    __shared__ float measS[MCTA][2];
    __shared__ float part[NWARPS][MCTA][9];
    __shared__ float bm0s[256], bm1s[256], bias2s[768], biasSs[8];
    __shared__ __align__(16) float4 smallWs[768];

    const int tid = threadIdx.x;
    const int w = tid >> 5, lane = tid & 31;
    const int b0 = blockIdx.x * MCTA;
    const int row0 = lane >> 2;
    const int cbase = (lane & 3) * 2;

    // ---- one-time shared init ----
    if (tid < 256) { bm0s[tid] = bm0[tid]; bm1s[tid] = bm1[tid]; }
    for (int i = tid; i < 768; i += NTHREADS) {
        bias2s[i] = (i < 256) ? bf10[i] : (i < 512 ? bf20[i - 256] : bh0[i - 512]);
        smallWs[i] = g_smallW4[i];
    }
    if (tid < 8)
        biasSs[tid] = (tid < 2) ? bf11[tid] : (tid < 6 ? bf21[tid - 2] : bh1[tid - 6]);
    for (int i = tid; i < MCTA * 24; i += NTHREADS) {   // zero cols 256..279
        int r = i / 24, c = 256 + i % 24;
        act[r][c] = __float2bfloat16(0.f);
    }
    for (int i = tid; i < MCTA * 256; i += NTHREADS) {  // c = c0
        int r = i >> 8, j = i & 255;
        act[r][j] = __float2bfloat16(c0[(size_t)(b0 + r) * 256 + j]);
    }
    __syncthreads();
    if (tid < MCTA) {
        int r = tid;
        float4 tg = *reinterpret_cast<const float4*>(
            &target[((size_t)(b0 + r) * T_STEPS) * 4]);
        sS[r][0] = tg.x; sS[r][1] = tg.y; sS[r][2] = tg.z; sS[r][3] = tg.w;
#pragma unroll
        for (int i = 0; i < 16; i++) Pm[r][i] = (i % 5 == 0) ? 1.f : 0.f;
        *reinterpret_cast<unsigned*>(&act[r][258]) =
            packbf2(tg.x * (1.f / 60.f), tg.y * (1.f / 60.f));
        *reinterpret_cast<unsigned*>(&act[r][260]) =
            packbf2(tg.z * (1.f / 60.f), tg.w * (1.f / 60.f));
    }
    __syncthreads();

    const unsigned ab0 =
        (unsigned)__cvta_generic_to_shared(&act[lane & 15][(lane >> 4) * 8]);
    const uint2* wG1 = g_Wpk + w * KSTEPS * 32 + lane;
    const uint2* wP3 = g_Wpk + (32 + 4 * w) * KSTEPS * 32 + lane;

    for (int t = 0; t < T_STEPS; t++) {
        // ---- P1: GEMM1 (cu preactivation), 1 tile/warp ----
        float D1[4];
        D1[0] = D1[1] = D1[2] = D1[3] = 0.f;
        {
            unsigned a[2][4];
            uint2 b1[2];
            b1[0] = wG1[0];
            b1[1] = wG1[32];
            ldmA(a[0], ab0);
#pragma unroll
            for (int ks = 0; ks < KSTEPS; ks++) {
                if (ks + 1 < KSTEPS)
                    ldmA(a[(ks + 1) & 1], ab0 + (unsigned)(ks + 1) * 32u);
                mma16816(D1, a[ks & 1], b1[ks & 1]);
                if (ks + 2 < KSTEPS)
                    b1[ks & 1] = wG1[(ks + 2) * 32];
            }
        }
        __syncthreads();

        // ---- P2: write cu over c; load meas; write m2 ----
        write_act_tanh(w, cbase, row0, D1, bm0s, act);
        if (tid < MCTA) {
            int r = tid;
            float2 m = *reinterpret_cast<const float2*>(
                &x[(((size_t)(b0 + r)) * T_STEPS + t) * 2]);
            measS[r][0] = m.x; measS[r][1] = m.y;
            *reinterpret_cast<unsigned*>(&act[r][256]) =
                packbf2(m.x * (1.f / 60.f), m.y * (1.f / 60.f));
        }
        __syncthreads();

        // ---- P3: fused GEMM2 (3 tiles) + GEMM3 ks0..15 (1 tile) ----
        uint2 b3l = wP3[(3 * KSTEPS + 16) * 32];
        float D2[4][4];
#pragma unroll
        for (int i = 0; i < 4; i++)
            D2[i][0] = D2[i][1] = D2[i][2] = D2[i][3] = 0.f;
        {
            unsigned a[2][4];
            uint2 b[4][2];
#pragma unroll
            for (int i = 0; i < 4; i++) {
                b[i][0] = wP3[(i * KSTEPS + 0) * 32];
                b[i][1] = wP3[(i * KSTEPS + 1) * 32];
            }
            ldmA(a[0], ab0);
#pragma unroll
            for (int ks = 0; ks < KSTEPS; ks++) {
                if (ks + 1 < KSTEPS)
                    ldmA(a[(ks + 1) & 1], ab0 + (unsigned)(ks + 1) * 32u);
#pragma unroll
                for (int i = 0; i < 4; i++) {
                    if (i < 3 || ks < KSTEPS - 1)
                        mma16816(D2[i], a[ks & 1], b[i][ks & 1]);
                    if (ks + 2 < KSTEPS)
                        b[i][ks & 1] = wP3[(i * KSTEPS + ks + 2) * 32];
                }
            }
        }
        float o[2][8];
#pragma unroll
        for (int s = 0; s < 2; s++)
#pragma unroll
            for (int k = 0; k < 8; k++) o[s][k] = 0.f;
#pragma unroll
        for (int j = 0; j < 3; j++)
            g2_epilogue(3 * w + j, cbase, D2[j], bias2s, smallWs, o);
#pragma unroll
        for (int s = 0; s < 2; s++)
#pragma unroll
            for (int k = 0; k < 8; k++) {
                o[s][k] += __shfl_xor_sync(0xffffffffu, o[s][k], 1);
                o[s][k] += __shfl_xor_sync(0xffffffffu, o[s][k], 2);
            }
        if ((lane & 3) == 0) {
#pragma unroll
            for (int k = 0; k < 8; k++) {
                part[w][row0][k]     = o[0][k];
                part[w][row0 + 8][k] = o[1][k];
            }
        }
        __syncthreads();

        // ---- P4: per-row Kalman update (fp32), tid<16 ----
        if (tid < MCTA) {
            const int r = tid;
            float sm[8];
#pragma unroll
            for (int k = 0; k < 8; k++) {
                float a = biasSs[k];
#pragma unroll
                for (int ww = 0; ww < NWARPS; ww++) a += part[ww][r][k];
                sm[k] = a;
            }
            const float d0 = sm[0], d1 = sm[1];
            const float pv[4] = {sm[2], sm[3], sm[4], sm[5]};
            const float hv0 = sm[6], hv1 = sm[7];
            float s0 = sS[r][0], s1 = sS[r][1], s2 = sS[r][2], s3 = sS[r][3];
            float sp[4];
            sp[0] = s0 + s2 + 0.5f * d0;
            sp[1] = s1 + s3 + 0.5f * d1;
            sp[2] = s2 + d0;
            sp[3] = s3 + d1;
            float P[4][4];
#pragma unroll
            for (int i = 0; i < 4; i++)
#pragma unroll
                for (int j = 0; j < 4; j++) P[i][j] = Pm[r][i * 4 + j];
            float FP[4][4], Pp[4][4];
#pragma unroll
            for (int j = 0; j < 4; j++) {
                FP[0][j] = P[0][j] + P[2][j];
                FP[1][j] = P[1][j] + P[3][j];
                FP[2][j] = P[2][j];
                FP[3][j] = P[3][j];
            }
#pragma unroll
            for (int i = 0; i < 4; i++) {
                Pp[i][0] = FP[i][0] + FP[i][2];
                Pp[i][1] = FP[i][1] + FP[i][3];
                Pp[i][2] = FP[i][2];
                Pp[i][3] = FP[i][3];
            }
#pragma unroll
            for (int i = 0; i < 4; i++)
#pragma unroll
                for (int j = 0; j < 4; j++) Pp[i][j] += pv[i] * pv[j];
#pragma unroll
            for (int i = 0; i < 4; i++) Pp[i][i] += 0.01f;
            float m0 = measS[r][0], m1 = measS[r][1];
            float in0 = m0 - sp[0], in1 = m1 - sp[1];
            float S00 = Pp[0][0] + hv0 * hv0 + 1.f;
            float S01 = Pp[0][1] + hv0 * hv1;
            float S10 = Pp[1][0] + hv1 * hv0;
            float S11 = Pp[1][1] + hv1 * hv1 + 1.f;
            float inv = 1.0f / (S00 * S11 - S01 * S10);
            float K[4][2], KS[4][2], su[4];
#pragma unroll
            for (int i = 0; i < 4; i++) {
                K[i][0] = (Pp[i][0] * S11 - Pp[i][1] * S10) * inv;
                K[i][1] = (Pp[i][1] * S00 - Pp[i][0] * S01) * inv;
                su[i] = sp[i] + K[i][0] * in0 + K[i][1] * in1;
                KS[i][0] = K[i][0] * S00 + K[i][1] * S10;
                KS[i][1] = K[i][0] * S01 + K[i][1] * S11;
            }
#pragma unroll
            for (int i = 0; i < 4; i++)
#pragma unroll
                for (int j = 0; j < 4; j++)
                    Pm[r][i * 4 + j] =
                        Pp[i][j] - KS[i][0] * K[j][0] - KS[i][1] * K[j][1];
            sS[r][0] = su[0]; sS[r][1] = su[1];
            sS[r][2] = su[2]; sS[r][3] = su[3];
            *reinterpret_cast<float4*>(
                &out[(((size_t)(b0 + r)) * T_STEPS + t) * 4]) =
                make_float4(su[0], su[1], su[2], su[3]);
            *reinterpret_cast<unsigned*>(&act[r][258]) =
                packbf2(su[0] * (1.f / 60.f), su[1] * (1.f / 60.f));
            *reinterpret_cast<unsigned*>(&act[r][260]) =
                packbf2(su[2] * (1.f / 60.f), su[3] * (1.f / 60.f));
        }
        __syncthreads();

        // ---- P5: GEMM3 final kstep (reads tail cols 256..271) + c_new.
        //      Reads only cols 256..271, writes only cols 0..255: disjoint. ----
        {
            unsigned a0[4];
            ldmA(a0, ab0 + 16u * 32u);
            mma16816(D2[3], a0, b3l);
        }
        write_act_tanh(w, cbase, row0, D2[3], bm1s, act);
        __syncthreads();
    }
}

// ---------------------------------------------------------------------------
extern "C" void kernel_launch(void* const* d_in, const int* in_sizes, int n_in,
                              void* d_out, int out_size)
{
    const float* x    = (const float*)d_in[0];
    const float* targ = (const float*)d_in[1];
    const float* c0   = (const float*)d_in[2];
    const float* Wm0  = (const float*)d_in[3];
    const float* bm0  = (const float*)d_in[4];
    const float* Wm1  = (const float*)d_in[5];
    const float* bm1  = (const float*)d_in[6];
    const float* Wf10 = (const float*)d_in[7];
    const float* bf10 = (const float*)d_in[8];
    const float* Wf11 = (const float*)d_in[9];
    const float* bf11 = (const float*)d_in[10];
    const float* Wf20 = (const float*)d_in[11];
    const float* bf20 = (const float*)d_in[12];
    const float* Wf21 = (const float*)d_in[13];
    const float* bf21 = (const float*)d_in[14];
    const float* Wh0  = (const float*)d_in[15];
    const float* bh0  = (const float*)d_in[16];
    const float* Wh1  = (const float*)d_in[17];
    const float* bh1  = (const float*)d_in[18];
    float* out = (float*)d_out;

    const int tot = 160 * 17 * 32 * 2 + 768;
    prepack_kernel<<<(tot + 255) / 256, 256>>>(Wm0, Wf10, Wf20, Wh0, Wm1,
                                               Wf11, Wf21, Wh1);
    egbrnn_main<<<NCTAS, NTHREADS>>>(x, targ, c0, bm0, bm1, bf10, bf11,
                                     bf20, bf21, bh0, bh1, out);
}

// round 14
// speedup vs baseline: 1.2989x; 1.2763x over previous
#include <cuda_runtime.h>
#include <cuda_bf16.h>

#define MCTA 16
#define NCTAS 128
#define NTHREADS 512
#define NWARPS 16
#define T_STEPS 128
#define KSTEPS 17
#define ACT_STRIDE 280   // bf16 elems per row (conflict-free ldmatrix)

// Packed weights, fragment order. Tile map (16 warps):
//   T in [0,32):    GEMM1 (Wm0), warp w owns T = 2w, 2w+1 (N cols [16w,16w+16))
//   T in [32,160):  per-warp P3 block: q=T-32, w=q/8, j=q%8
//                   j<6  -> GEMM2 tile tg=(6w+j)  (Wf10|Wf20|Wh0, n2=8*tg)
//                   j>=6 -> GEMM3 (Wm1) n-tile 2w+(j-6)
__device__ uint2 g_Wpk[160 * 17 * 32];
__device__ float4 g_smallW4[768];

// ---------------------------------------------------------------------------
// Activation column layout (padded K = 272):
//   0..255: c / cu / c_new    256..257: meas/60    258..261: s/60   262..271: 0
// Row remap: type0 (Wm0,Wf10,Wf20;fin260): k<256->k, 258..261->k-2
//            type1 (Wh0;fin262): k<256->k, 256,257->k+4, 258..261->k-2
//            type2 (Wm1;fin262): identity
// ---------------------------------------------------------------------------
__global__ void prepack_kernel(
    const float* __restrict__ Wm0, const float* __restrict__ Wf10,
    const float* __restrict__ Wf20, const float* __restrict__ Wh0,
    const float* __restrict__ Wm1, const float* __restrict__ Wf11,
    const float* __restrict__ Wf21, const float* __restrict__ Wh1)
{
    const int total_u32 = 160 * 17 * 32 * 2;
    int idx = blockIdx.x * blockDim.x + threadIdx.x;
    if (idx < total_u32) {
        int r    = idx & 1;
        int lane = (idx >> 1) & 31;
        int tk   = idx >> 6;          // tile*17 + ks
        int ks   = tk % 17;
        int tile = tk / 17;
        int kk = ks * 16 + (lane & 3) * 2 + r * 8;
        const float* W; int type; int ncol;
        if (tile < 32) {
            W = Wm0; type = 0; ncol = tile * 8 + (lane >> 2);
        } else {
            int q = tile - 32, wq = q >> 3, j = q & 7;
            if (j < 6) {
                int n2 = (wq * 6 + j) * 8 + (lane >> 2);
                if (n2 < 256)      { W = Wf10; type = 0; ncol = n2; }
                else if (n2 < 512) { W = Wf20; type = 0; ncol = n2 - 256; }
                else               { W = Wh0;  type = 1; ncol = n2 - 512; }
            } else {
                W = Wm1; type = 2; ncol = (wq * 2 + (j - 6)) * 8 + (lane >> 2);
            }
        }
        auto srcrow = [&](int k) -> int {
            if (type == 0) return k < 256 ? k : ((k >= 258 && k < 262) ? k - 2 : -1);
            if (type == 1) return k < 256 ? k : (k < 258 ? k + 4 : (k < 262 ? k - 2 : -1));
            return k < 262 ? k : -1;
        };
        int s0 = srcrow(kk), s1 = srcrow(kk + 1);
        float v0 = (s0 >= 0) ? W[(size_t)s0 * 256 + ncol] : 0.f;
        float v1 = (s1 >= 0) ? W[(size_t)s1 * 256 + ncol] : 0.f;
        __nv_bfloat162 p;
        p.x = __float2bfloat16(v0);
        p.y = __float2bfloat16(v1);
        reinterpret_cast<unsigned*>(g_Wpk)[idx] = *reinterpret_cast<unsigned*>(&p);
    } else if (idx < total_u32 + 768) {
        int j = idx - total_u32;
        float4 v = make_float4(0.f, 0.f, 0.f, 0.f);
        if (j < 256)      { v.x = Wf11[j * 2];        v.y = Wf11[j * 2 + 1]; }
        else if (j < 512) { int q = j - 256;
                            v.x = Wf21[q * 4]; v.y = Wf21[q * 4 + 1];
                            v.z = Wf21[q * 4 + 2]; v.w = Wf21[q * 4 + 3]; }
        else              { int q = j - 512;
                            v.x = Wh1[q * 2];  v.y = Wh1[q * 2 + 1]; }
        g_smallW4[j] = v;
    }
}

// ---------------------------------------------------------------------------
__device__ __forceinline__ void mma16816(float* d, const unsigned* a, uint2 b) {
    asm volatile(
        "mma.sync.aligned.m16n8k16.row.col.f32.bf16.bf16.f32 "
        "{%0,%1,%2,%3}, {%4,%5,%6,%7}, {%8,%9}, {%0,%1,%2,%3};\n"
        : "+f"(d[0]), "+f"(d[1]), "+f"(d[2]), "+f"(d[3])
        : "r"(a[0]), "r"(a[1]), "r"(a[2]), "r"(a[3]), "r"(b.x), "r"(b.y));
}
__device__ __forceinline__ void ldmA(unsigned* a, unsigned addr) {
    asm volatile(
        "ldmatrix.sync.aligned.m8n8.x4.shared.b16 {%0,%1,%2,%3}, [%4];\n"
        : "=r"(a[0]), "=r"(a[1]), "=r"(a[2]), "=r"(a[3]) : "r"(addr));
}
__device__ __forceinline__ float tanha(float x) {
    float y; asm("tanh.approx.f32 %0, %1;" : "=f"(y) : "f"(x)); return y;
}
__device__ __forceinline__ unsigned packbf2(float a, float b) {
    __nv_bfloat162 h;
    h.x = __float2bfloat16(a);
    h.y = __float2bfloat16(b);
    return *reinterpret_cast<unsigned*>(&h);
}

__device__ __forceinline__ void write_act_tanh(int ntile, int cbase, int row0,
        const float (&D)[4], const float* __restrict__ bias,
        __nv_bfloat16 (*actp)[ACT_STRIDE]) {
    int col = ntile * 8 + cbase;
    float bv0 = bias[col], bv1 = bias[col + 1];
    __nv_bfloat162 h0, h1;
    h0.x = __float2bfloat16(tanha(D[0] + bv0));
    h0.y = __float2bfloat16(tanha(D[1] + bv1));
    h1.x = __float2bfloat16(tanha(D[2] + bv0));
    h1.y = __float2bfloat16(tanha(D[3] + bv1));
    *reinterpret_cast<__nv_bfloat162*>(&actp[row0][col]) = h0;
    *reinterpret_cast<__nv_bfloat162*>(&actp[row0 + 8][col]) = h1;
}

__device__ __forceinline__ void g2_epilogue(int tg, int cbase,
        const float (&D)[4], const float* __restrict__ bias2s,
        const float4* __restrict__ smallWs, float (&o)[2][8]) {
    int col = tg * 8 + cbase;
    int seg = tg >> 5;  // 0: Wf11 (d), 1: Wf21 (pv), 2: Wh1 (hv)
    float bb0 = bias2s[col], bb1 = bias2s[col + 1];
    float4 w0 = smallWs[col];
    float4 w1 = smallWs[col + 1];
    int ob = (seg == 0) ? 0 : ((seg == 1) ? 2 : 6);
    float h0 = tanha(D[0] + bb0);
    float h1 = tanha(D[1] + bb1);
    float h2 = tanha(D[2] + bb0);
    float h3 = tanha(D[3] + bb1);
    o[0][ob + 0] += h0 * w0.x + h1 * w1.x;
    o[0][ob + 1] += h0 * w0.y + h1 * w1.y;
    o[1][ob + 0] += h2 * w0.x + h3 * w1.x;
    o[1][ob + 1] += h2 * w0.y + h3 * w1.y;
    if (seg == 1) {
        o[0][ob + 2] += h0 * w0.z + h1 * w1.z;
        o[0][ob + 3] += h0 * w0.w + h1 * w1.w;
        o[1][ob + 2] += h2 * w0.z + h3 * w1.z;
        o[1][ob + 3] += h2 * w0.w + h3 * w1.w;
    }
}

// ---------------------------------------------------------------------------
// Main persistent kernel: 128 CTAs x 512 threads, 16 batch rows per CTA.
// R5 champion structure (5 barriers) + meas reg-prefetch + b3l in P2 +
// float4-packed partials. No other changes.
// ---------------------------------------------------------------------------
__global__ void __launch_bounds__(NTHREADS, 1) egbrnn_main(
    const float* __restrict__ x, const float* __restrict__ target,
    const float* __restrict__ c0,
    const float* __restrict__ bm0, const float* __restrict__ bm1,
    const float* __restrict__ bf10, const float* __restrict__ bf11,
    const float* __restrict__ bf20, const float* __restrict__ bf21,
    const float* __restrict__ bh0, const float* __restrict__ bh1,
    float* __restrict__ out)
{
    __shared__ __align__(16) __nv_bfloat16 act[MCTA][ACT_STRIDE];
    __shared__ float sS[MCTA][4];
    __shared__ float Pm[MCTA][16];
    __shared__ __align__(16) float part[NWARPS][MCTA][12];
    __shared__ float bm0s[256], bm1s[256], bias2s[768], biasSs[8];
    __shared__ __align__(16) float4 smallWs[768];

    const int tid = threadIdx.x;
    const int w = tid >> 5, lane = tid & 31;
    const int b0 = blockIdx.x * MCTA;
    const int row0 = lane >> 2;
    const int cbase = (lane & 3) * 2;

    // ---- one-time shared init ----
    if (tid < 256) { bm0s[tid] = bm0[tid]; bm1s[tid] = bm1[tid]; }
    for (int i = tid; i < 768; i += NTHREADS) {
        bias2s[i] = (i < 256) ? bf10[i] : (i < 512 ? bf20[i - 256] : bh0[i - 512]);
        smallWs[i] = g_smallW4[i];
    }
    if (tid < 8)
        biasSs[tid] = (tid < 2) ? bf11[tid] : (tid < 6 ? bf21[tid - 2] : bh1[tid - 6]);
    for (int i = tid; i < MCTA * 24; i += NTHREADS) {   // zero cols 256..279
        int r = i / 24, c = 256 + i % 24;
        act[r][c] = __float2bfloat16(0.f);
    }
    for (int i = tid; i < MCTA * 256; i += NTHREADS) {  // c = c0
        int r = i >> 8, j = i & 255;
        act[r][j] = __float2bfloat16(c0[(size_t)(b0 + r) * 256 + j]);
    }
    __syncthreads();
    if (tid < MCTA) {
        int r = tid;
        float4 tg = *reinterpret_cast<const float4*>(
            &target[((size_t)(b0 + r) * T_STEPS) * 4]);
        sS[r][0] = tg.x; sS[r][1] = tg.y; sS[r][2] = tg.z; sS[r][3] = tg.w;
#pragma unroll
        for (int i = 0; i < 16; i++) Pm[r][i] = (i % 5 == 0) ? 1.f : 0.f;
        *reinterpret_cast<unsigned*>(&act[r][258]) =
            packbf2(tg.x * (1.f / 60.f), tg.y * (1.f / 60.f));
        *reinterpret_cast<unsigned*>(&act[r][260]) =
            packbf2(tg.z * (1.f / 60.f), tg.w * (1.f / 60.f));
    }
    __syncthreads();

    const unsigned ab0 =
        (unsigned)__cvta_generic_to_shared(&act[lane & 15][(lane >> 4) * 8]);
    const uint2* wG1 = g_Wpk + (2 * w) * KSTEPS * 32 + lane;
    const uint2* wP3 = g_Wpk + (32 + 8 * w) * KSTEPS * 32 + lane;

    // meas register prefetch (meaningful for tid<16 only)
    float2 xcur, xnxt;
    if (tid < MCTA)
        xcur = *reinterpret_cast<const float2*>(
            &x[((size_t)(b0 + tid)) * T_STEPS * 2]);

    for (int t = 0; t < T_STEPS; t++) {
        // ---- P1: GEMM1 (cu preactivation), 2 tiles/warp ----
        float D1[2][4];
#pragma unroll
        for (int i = 0; i < 2; i++)
            D1[i][0] = D1[i][1] = D1[i][2] = D1[i][3] = 0.f;
        {
            unsigned a[2][4];
            uint2 b1[2][2];
            b1[0][0] = wG1[0];
            b1[1][0] = wG1[KSTEPS * 32];
            b1[0][1] = wG1[32];
            b1[1][1] = wG1[(KSTEPS + 1) * 32];
            ldmA(a[0], ab0);
#pragma unroll
            for (int ks = 0; ks < KSTEPS; ks++) {
                if (ks + 1 < KSTEPS)
                    ldmA(a[(ks + 1) & 1], ab0 + (unsigned)(ks + 1) * 32u);
                mma16816(D1[0], a[ks & 1], b1[0][ks & 1]);
                mma16816(D1[1], a[ks & 1], b1[1][ks & 1]);
                if (ks + 2 < KSTEPS) {
                    b1[0][ks & 1] = wG1[(0 * KSTEPS + ks + 2) * 32];
                    b1[1][ks & 1] = wG1[(1 * KSTEPS + ks + 2) * 32];
                }
            }
        }
        __syncthreads();

        // ---- P2: write cu over c; m2 from reg; b3l loads; next-meas load --
        write_act_tanh(2 * w,     cbase, row0, D1[0], bm0s, act);
        write_act_tanh(2 * w + 1, cbase, row0, D1[1], bm0s, act);
        uint2 b3l[2];
        b3l[0] = wP3[(6 * KSTEPS + 16) * 32];
        b3l[1] = wP3[(7 * KSTEPS + 16) * 32];
        if (tid < MCTA) {
            *reinterpret_cast<unsigned*>(&act[tid][256]) =
                packbf2(xcur.x * (1.f / 60.f), xcur.y * (1.f / 60.f));
            int tn = (t + 1 < T_STEPS) ? t + 1 : t;
            xnxt = *reinterpret_cast<const float2*>(
                &x[(((size_t)(b0 + tid)) * T_STEPS + tn) * 2]);
        }
        __syncthreads();

        // ---- P3: fused GEMM2 (6 tiles) + GEMM3 ks0..15 (2 tiles) ----
        float D2[8][4];
#pragma unroll
        for (int i = 0; i < 8; i++)
            D2[i][0] = D2[i][1] = D2[i][2] = D2[i][3] = 0.f;
        {
            unsigned a[2][4];
            uint2 b[8][2];
#pragma unroll
            for (int i = 0; i < 8; i++) {
                b[i][0] = wP3[(i * KSTEPS + 0) * 32];
                b[i][1] = wP3[(i * KSTEPS + 1) * 32];
            }
            ldmA(a[0], ab0);
#pragma unroll
            for (int ks = 0; ks < KSTEPS; ks++) {
                if (ks + 1 < KSTEPS)
                    ldmA(a[(ks + 1) & 1], ab0 + (unsigned)(ks + 1) * 32u);
#pragma unroll
                for (int i = 0; i < 8; i++) {
                    if (i < 6 || ks < KSTEPS - 1)
                        mma16816(D2[i], a[ks & 1], b[i][ks & 1]);
                    if (ks + 2 < KSTEPS)
                        b[i][ks & 1] = wP3[(i * KSTEPS + ks + 2) * 32];
                }
            }
        }
        float o[2][8];
#pragma unroll
        for (int s = 0; s < 2; s++)
#pragma unroll
            for (int k = 0; k < 8; k++) o[s][k] = 0.f;
#pragma unroll
        for (int j = 0; j < 6; j++)
            g2_epilogue(6 * w + j, cbase, D2[j], bias2s, smallWs, o);
#pragma unroll
        for (int s = 0; s < 2; s++)
#pragma unroll
            for (int k = 0; k < 8; k++) {
                o[s][k] += __shfl_xor_sync(0xffffffffu, o[s][k], 1);
                o[s][k] += __shfl_xor_sync(0xffffffffu, o[s][k], 2);
            }
        if ((lane & 3) == 0) {
            float4* p0 = reinterpret_cast<float4*>(part[w][row0]);
            float4* p1 = reinterpret_cast<float4*>(part[w][row0 + 8]);
            p0[0] = make_float4(o[0][0], o[0][1], o[0][2], o[0][3]);
            p0[1] = make_float4(o[0][4], o[0][5], o[0][6], o[0][7]);
            p1[0] = make_float4(o[1][0], o[1][1], o[1][2], o[1][3]);
            p1[1] = make_float4(o[1][4], o[1][5], o[1][6], o[1][7]);
        }
        __syncthreads();

        // ---- P4: per-row Kalman update (fp32), tid<16, float4 reduce ----
        if (tid < MCTA) {
            const int r = tid;
            float sm[8];
#pragma unroll
            for (int k = 0; k < 8; k++) sm[k] = biasSs[k];
#pragma unroll
            for (int ww = 0; ww < NWARPS; ww++) {
                const float4* pp = reinterpret_cast<const float4*>(part[ww][r]);
                float4 v0 = pp[0], v1 = pp[1];
                sm[0] += v0.x; sm[1] += v0.y; sm[2] += v0.z; sm[3] += v0.w;
                sm[4] += v1.x; sm[5] += v1.y; sm[6] += v1.z; sm[7] += v1.w;
            }
            const float d0 = sm[0], d1 = sm[1];
            const float pv[4] = {sm[2], sm[3], sm[4], sm[5]};
            const float hv0 = sm[6], hv1 = sm[7];
            float s0 = sS[r][0], s1 = sS[r][1], s2 = sS[r][2], s3 = sS[r][3];
            float sp[4];
            sp[0] = s0 + s2 + 0.5f * d0;
            sp[1] = s1 + s3 + 0.5f * d1;
            sp[2] = s2 + d0;
            sp[3] = s3 + d1;
            float P[4][4];
#pragma unroll
            for (int i = 0; i < 4; i++)
#pragma unroll
                for (int j = 0; j < 4; j++) P[i][j] = Pm[r][i * 4 + j];
            float FP[4][4], Pp[4][4];
#pragma unroll
            for (int j = 0; j < 4; j++) {
                FP[0][j] = P[0][j] + P[2][j];
                FP[1][j] = P[1][j] + P[3][j];
                FP[2][j] = P[2][j];
                FP[3][j] = P[3][j];
            }
#pragma unroll
            for (int i = 0; i < 4; i++) {
                Pp[i][0] = FP[i][0] + FP[i][2];
                Pp[i][1] = FP[i][1] + FP[i][3];
                Pp[i][2] = FP[i][2];
                Pp[i][3] = FP[i][3];
            }
#pragma unroll
            for (int i = 0; i < 4; i++)
#pragma unroll
                for (int j = 0; j < 4; j++) Pp[i][j] += pv[i] * pv[j];
#pragma unroll
            for (int i = 0; i < 4; i++) Pp[i][i] += 0.01f;
            float m0 = xcur.x, m1 = xcur.y;
            float in0 = m0 - sp[0], in1 = m1 - sp[1];
            float S00 = Pp[0][0] + hv0 * hv0 + 1.f;
            float S01 = Pp[0][1] + hv0 * hv1;
            float S10 = Pp[1][0] + hv1 * hv0;
            float S11 = Pp[1][1] + hv1 * hv1 + 1.f;
            float inv = 1.0f / (S00 * S11 - S01 * S10);
            float K[4][2], KS[4][2], su[4];
#pragma unroll
            for (int i = 0; i < 4; i++) {
                K[i][0] = (Pp[i][0] * S11 - Pp[i][1] * S10) * inv;
                K[i][1] = (Pp[i][1] * S00 - Pp[i][0] * S01) * inv;
                su[i] = sp[i] + K[i][0] * in0 + K[i][1] * in1;
                KS[i][0] = K[i][0] * S00 + K[i][1] * S10;
                KS[i][1] = K[i][0] * S01 + K[i][1] * S11;
            }
#pragma unroll
            for (int i = 0; i < 4; i++)
#pragma unroll
                for (int j = 0; j < 4; j++)
                    Pm[r][i * 4 + j] =
                        Pp[i][j] - KS[i][0] * K[j][0] - KS[i][1] * K[j][1];
            sS[r][0] = su[0]; sS[r][1] = su[1];
            sS[r][2] = su[2]; sS[r][3] = su[3];
            *reinterpret_cast<float4*>(
                &out[(((size_t)(b0 + r)) * T_STEPS + t) * 4]) =
                make_float4(su[0], su[1], su[2], su[3]);
            *reinterpret_cast<unsigned*>(&act[r][258]) =
                packbf2(su[0] * (1.f / 60.f), su[1] * (1.f / 60.f));
            *reinterpret_cast<unsigned*>(&act[r][260]) =
                packbf2(su[2] * (1.f / 60.f), su[3] * (1.f / 60.f));
            xcur = xnxt;
        }
        __syncthreads();

        // ---- P5: GEMM3 final kstep (reads tail cols 256..271) + c_new.
        //      Reads only cols 256..271, writes only cols 0..255: disjoint. ----
        {
            unsigned a0[4];
            ldmA(a0, ab0 + 16u * 32u);
            mma16816(D2[6], a0, b3l[0]);
            mma16816(D2[7], a0, b3l[1]);
        }
        write_act_tanh(2 * w,     cbase, row0, D2[6], bm1s, act);
        write_act_tanh(2 * w + 1, cbase, row0, D2[7], bm1s, act);
        __syncthreads();
    }
}

// ---------------------------------------------------------------------------
extern "C" void kernel_launch(void* const* d_in, const int* in_sizes, int n_in,
                              void* d_out, int out_size)
{
    const float* x    = (const float*)d_in[0];
    const float* targ = (const float*)d_in[1];
    const float* c0   = (const float*)d_in[2];
    const float* Wm0  = (const float*)d_in[3];
    const float* bm0  = (const float*)d_in[4];
    const float* Wm1  = (const float*)d_in[5];
    const float* bm1  = (const float*)d_in[6];
    const float* Wf10 = (const float*)d_in[7];
    const float* bf10 = (const float*)d_in[8];
    const float* Wf11 = (const float*)d_in[9];
    const float* bf11 = (const float*)d_in[10];
    const float* Wf20 = (const float*)d_in[11];
    const float* bf20 = (const float*)d_in[12];
    const float* Wf21 = (const float*)d_in[13];
    const float* bf21 = (const float*)d_in[14];
    const float* Wh0  = (const float*)d_in[15];
    const float* bh0  = (const float*)d_in[16];
    const float* Wh1  = (const float*)d_in[17];
    const float* bh1  = (const float*)d_in[18];
    float* out = (float*)d_out;

    const int tot = 160 * 17 * 32 * 2 + 768;
    prepack_kernel<<<(tot + 255) / 256, 256>>>(Wm0, Wf10, Wf20, Wh0, Wm1,
                                               Wf11, Wf21, Wh1);
    egbrnn_main<<<NCTAS, NTHREADS>>>(x, targ, c0, bm0, bm1, bf10, bf11,
                                     bf20, bf21, bh0, bh1, out);
}